// round 2
// baseline (speedup 1.0000x reference)
#include <cuda_runtime.h>
#include <cuda_bf16.h>
#include <cstdint>

#define N_NODES 16384
#define N_EDGES 262144
#define N_GRAPHS 16
#define IN_CH 128
#define HID_CH 256
#define LAT 64

// d_out offsets (floats): z_node, z_graph, x_hat, a_hat
#define Z_OFF   0
#define ZG_OFF  (N_NODES*LAT)                    // 1048576
#define XH_OFF  (ZG_OFF + N_GRAPHS*LAT)          // 1049600
#define AH_OFF  (XH_OFF + N_NODES*IN_CH)         // 3146752

// ---------------- device scratch (no allocation allowed) ----------------
__device__ float g_h[N_NODES*HID_CH];     // 16 MB: h = x@gcn_w^T, later h2
__device__ float g_agg[N_NODES*HID_CH];   // 16 MB: edge aggregation
__device__ float g_deg[N_NODES];
__device__ float g_dinv[N_NODES];
__device__ float g_norm[N_EDGES];
__device__ float g_zgsum[N_GRAPHS*LAT];
__device__ float g_cnt[N_GRAPHS];
__device__ float g_gout[N_GRAPHS*IN_CH];

// ---------------- small helpers ----------------
__device__ __forceinline__ unsigned cvt_tf32(float x) {
    unsigned u;
    asm("cvt.rna.tf32.f32 %0, %1;" : "=r"(u) : "f"(x));
    return u;
}

__device__ __forceinline__ float sigf(float x) {
    float t;
    asm("tanh.approx.f32 %0, %1;" : "=f"(t) : "f"(x * 0.5f));
    return fmaf(0.5f, t, 0.5f);
}

__device__ __forceinline__ void mma_tf32(float* c, const unsigned* a, const unsigned* b) {
    asm volatile(
        "mma.sync.aligned.m16n8k8.row.col.f32.tf32.tf32.f32 "
        "{%0,%1,%2,%3},{%4,%5,%6,%7},{%8,%9},{%0,%1,%2,%3};\n"
        : "+f"(c[0]), "+f"(c[1]), "+f"(c[2]), "+f"(c[3])
        : "r"(a[0]), "r"(a[1]), "r"(a[2]), "r"(a[3]), "r"(b[0]), "r"(b[1]));
}

// ---------------- stage kernels ----------------
__global__ void k_init() {
    int i = blockIdx.x * blockDim.x + threadIdx.x;
    if (i < N_NODES * HID_CH) g_agg[i] = 0.0f;
    if (i < N_NODES) g_deg[i] = 1.0f;          // self-loop contributes 1
    if (i < N_GRAPHS * LAT) g_zgsum[i] = 0.0f;
    if (i < N_GRAPHS) g_cnt[i] = 0.0f;
}

__global__ void k_deg(const int* __restrict__ ei) {
    int e = blockIdx.x * blockDim.x + threadIdx.x;
    if (e < N_EDGES) atomicAdd(&g_deg[ei[N_EDGES + e]], 1.0f);
}

__global__ void k_count(const int* __restrict__ batch) {
    int i = blockIdx.x * blockDim.x + threadIdx.x;
    if (i < N_NODES) atomicAdd(&g_cnt[batch[i]], 1.0f);
}

__global__ void k_dinv() {
    int i = blockIdx.x * blockDim.x + threadIdx.x;
    if (i < N_NODES) g_dinv[i] = rsqrtf(g_deg[i]);   // deg >= 1 always
}

__global__ void k_norm(const int* __restrict__ ei) {
    int e = blockIdx.x * blockDim.x + threadIdx.x;
    if (e < N_EDGES) {
        int r = ei[e];
        int c = ei[N_EDGES + e];
        g_norm[e] = g_dinv[r] * g_dinv[c];
    }
}

// C[m][n] = sum_k A[m][k] * B[n][k]; A: MxK row-major, B: NxK row-major.
// Tile 64x64, 256 threads, 4x4 per thread, K chunked by 16.
__global__ __launch_bounds__(256) void gemm_nt(
    const float* __restrict__ A, const float* __restrict__ B,
    float* __restrict__ C, int M, int Nc, int K)
{
    __shared__ float As[16][68];
    __shared__ float Bs[16][68];
    int tid = threadIdx.x;
    int tx = tid & 15, ty = tid >> 4;
    int m0 = blockIdx.y * 64, n0 = blockIdx.x * 64;
    int lrow = tid >> 2, lq = (tid & 3) * 4;

    float acc[4][4];
#pragma unroll
    for (int i = 0; i < 4; i++)
#pragma unroll
        for (int j = 0; j < 4; j++) acc[i][j] = 0.0f;

    for (int k0 = 0; k0 < K; k0 += 16) {
        float4 va = *(const float4*)&A[(size_t)(m0 + lrow) * K + k0 + lq];
        float4 vb = *(const float4*)&B[(size_t)(n0 + lrow) * K + k0 + lq];
        __syncthreads();
        As[lq + 0][lrow] = va.x; As[lq + 1][lrow] = va.y;
        As[lq + 2][lrow] = va.z; As[lq + 3][lrow] = va.w;
        Bs[lq + 0][lrow] = vb.x; Bs[lq + 1][lrow] = vb.y;
        Bs[lq + 2][lrow] = vb.z; Bs[lq + 3][lrow] = vb.w;
        __syncthreads();
#pragma unroll
        for (int k = 0; k < 16; k++) {
            float4 a = *(float4*)&As[k][ty * 4];
            float4 b = *(float4*)&Bs[k][tx * 4];
            float av[4] = {a.x, a.y, a.z, a.w};
            float bv[4] = {b.x, b.y, b.z, b.w};
#pragma unroll
            for (int i = 0; i < 4; i++)
#pragma unroll
                for (int j = 0; j < 4; j++) acc[i][j] = fmaf(av[i], bv[j], acc[i][j]);
        }
    }
#pragma unroll
    for (int i = 0; i < 4; i++) {
        float4 v = make_float4(acc[i][0], acc[i][1], acc[i][2], acc[i][3]);
        *(float4*)&C[(size_t)(m0 + ty * 4 + i) * Nc + n0 + tx * 4] = v;
    }
}

// One block per edge: agg[col] += norm(e) * h[row]
__global__ __launch_bounds__(256) void k_scatter(const int* __restrict__ ei) {
    int e = blockIdx.x;
    int c = threadIdx.x;
    int row = ei[e];
    int col = ei[N_EDGES + e];
    float v = g_norm[e] * g_h[row * HID_CH + c];
    atomicAdd(&g_agg[col * HID_CH + c], v);
}

// h2 = relu(agg + dinv^2 * h (self-loop) + gcn_b), in-place into g_h
__global__ void k_relu(const float* __restrict__ gcn_b) {
    int i = blockIdx.x * blockDim.x + threadIdx.x;
    if (i < N_NODES * HID_CH) {
        int n = i / HID_CH, c = i % HID_CH;
        float di = g_dinv[n];
        float v = g_agg[i] + di * di * g_h[i] + gcn_b[c];
        g_h[i] = fmaxf(v, 0.0f);
    }
}

// add lin_b to z (in d_out), accumulate graph sums
__global__ void k_zbias(float* __restrict__ z, const float* __restrict__ lin_b,
                        const int* __restrict__ batch) {
    int i = blockIdx.x * blockDim.x + threadIdx.x;
    if (i < N_NODES * LAT) {
        int n = i / LAT, c = i % LAT;
        float v = z[i] + lin_b[c];
        z[i] = v;
        atomicAdd(&g_zgsum[batch[n] * LAT + c], v);
    }
}

__global__ void k_zg(float* __restrict__ zg_out) {
    int i = blockIdx.x * blockDim.x + threadIdx.x;
    if (i < N_GRAPHS * LAT) {
        int g = i / LAT;
        zg_out[i] = g_zgsum[i] / fmaxf(g_cnt[g], 1.0f);
    }
}

// g_out[g][c] = zg[g] . dec_w[c] + dec_b[c]
__global__ void k_gout(const float* __restrict__ zg, const float* __restrict__ dec_w,
                       const float* __restrict__ dec_b) {
    int g = blockIdx.x, c = threadIdx.x;
    float s = dec_b[c];
#pragma unroll 8
    for (int k = 0; k < LAT; k++) s = fmaf(zg[g * LAT + k], dec_w[c * LAT + k], s);
    g_gout[g * IN_CH + c] = s;
}

__global__ void k_xhat(float* __restrict__ xh, const int* __restrict__ batch) {
    int t = blockIdx.x * blockDim.x + threadIdx.x;   // N_NODES * 32 threads
    if (t < N_NODES * (IN_CH / 4)) {
        int n = t / (IN_CH / 4), q = t % (IN_CH / 4);
        int b = batch[n];
        float4 v = *(const float4*)&g_gout[b * IN_CH + q * 4];
        *(float4*)&xh[(size_t)n * IN_CH + q * 4] = v;
    }
}

// a_hat = sigmoid(Z @ Z^T), Z: [16384, 64] fp32 -> tf32 MMA.
// 128x128 tile per block, 8 warps (2x4), warp tile 64x32, K in 2 halves of 32.
__global__ __launch_bounds__(256) void k_ahat(const float* __restrict__ z,
                                              float* __restrict__ out) {
    __shared__ unsigned Zi[128][36];   // stride 36 (== 4 mod 32): conflict-free
    __shared__ unsigned Zj[128][36];
    int tid = threadIdx.x;
    int warp = tid >> 5, lane = tid & 31;
    int wm = warp >> 2, wn = warp & 3;
    int mb = blockIdx.y * 128, nb = blockIdx.x * 128;
    int r = lane >> 2, t4 = lane & 3;

    float acc[4][4][4];
#pragma unroll
    for (int mt = 0; mt < 4; mt++)
#pragma unroll
        for (int nt = 0; nt < 4; nt++)
#pragma unroll
            for (int q = 0; q < 4; q++) acc[mt][nt][q] = 0.0f;

#pragma unroll
    for (int kh = 0; kh < 2; kh++) {
        __syncthreads();
        // load 128x32 fp32 for each side, convert to tf32
#pragma unroll
        for (int f = 0; f < 4; f++) {
            int id = f * 256 + tid;          // 0..1023
            int row = id >> 3, q = id & 7;   // 8 float4 per row
            float4 vi = *(const float4*)&z[(size_t)(mb + row) * LAT + kh * 32 + q * 4];
            float4 vj = *(const float4*)&z[(size_t)(nb + row) * LAT + kh * 32 + q * 4];
            uint4 ui = make_uint4(cvt_tf32(vi.x), cvt_tf32(vi.y), cvt_tf32(vi.z), cvt_tf32(vi.w));
            uint4 uj = make_uint4(cvt_tf32(vj.x), cvt_tf32(vj.y), cvt_tf32(vj.z), cvt_tf32(vj.w));
            *(uint4*)&Zi[row][q * 4] = ui;
            *(uint4*)&Zj[row][q * 4] = uj;
        }
        __syncthreads();

#pragma unroll
        for (int k8 = 0; k8 < 4; k8++) {
            int kc = k8 * 8;
            unsigned a[4][4], b[4][2];
#pragma unroll
            for (int mt = 0; mt < 4; mt++) {
                int rb = wm * 64 + mt * 16;
                a[mt][0] = Zi[rb + r][kc + t4];
                a[mt][1] = Zi[rb + r + 8][kc + t4];
                a[mt][2] = Zi[rb + r][kc + t4 + 4];
                a[mt][3] = Zi[rb + r + 8][kc + t4 + 4];
            }
#pragma unroll
            for (int nt = 0; nt < 4; nt++) {
                int cb = wn * 32 + nt * 8;
                b[nt][0] = Zj[cb + r][kc + t4];
                b[nt][1] = Zj[cb + r][kc + t4 + 4];
            }
#pragma unroll
            for (int mt = 0; mt < 4; mt++)
#pragma unroll
                for (int nt = 0; nt < 4; nt++)
                    mma_tf32(acc[mt][nt], a[mt], b[nt]);
        }
    }

    // epilogue: sigmoid + store (float2 per fragment row)
#pragma unroll
    for (int mt = 0; mt < 4; mt++) {
#pragma unroll
        for (int nt = 0; nt < 4; nt++) {
            int gm = mb + wm * 64 + mt * 16 + r;
            int gn = nb + wn * 32 + nt * 8 + t4 * 2;
            float2 s0 = make_float2(sigf(acc[mt][nt][0]), sigf(acc[mt][nt][1]));
            float2 s1 = make_float2(sigf(acc[mt][nt][2]), sigf(acc[mt][nt][3]));
            *(float2*)&out[(size_t)gm * N_NODES + gn] = s0;
            *(float2*)&out[((size_t)gm + 8) * N_NODES + gn] = s1;
        }
    }
}

// ---------------- launcher ----------------
extern "C" void kernel_launch(void* const* d_in, const int* in_sizes, int n_in,
                              void* d_out_v, int out_size) {
    (void)in_sizes; (void)n_in; (void)out_size;
    const float* x        = (const float*)d_in[0];
    const int* ei         = (const int*)d_in[1];
    const int* bat        = (const int*)d_in[2];
    const float* gcn_w    = (const float*)d_in[3];
    const float* gcn_b    = (const float*)d_in[4];
    const float* lin_w    = (const float*)d_in[5];
    const float* lin_b    = (const float*)d_in[6];
    const float* dec_w    = (const float*)d_in[7];
    const float* dec_b    = (const float*)d_in[8];
    float* out = (float*)d_out_v;

    float *p_h;
    cudaGetSymbolAddress((void**)&p_h, g_h);

    k_init<<<(N_NODES * HID_CH + 255) / 256, 256>>>();
    k_deg<<<(N_EDGES + 255) / 256, 256>>>(ei);
    k_count<<<(N_NODES + 255) / 256, 256>>>(bat);
    k_dinv<<<(N_NODES + 255) / 256, 256>>>();
    k_norm<<<(N_EDGES + 255) / 256, 256>>>(ei);

    // h = x @ gcn_w^T  [16384,256]
    gemm_nt<<<dim3(HID_CH / 64, N_NODES / 64), 256>>>(x, gcn_w, p_h, N_NODES, HID_CH, IN_CH);

    k_scatter<<<N_EDGES, 256>>>(ei);
    k_relu<<<(N_NODES * HID_CH + 255) / 256, 256>>>(gcn_b);

    // z = h2 @ lin_w^T  [16384,64] -> d_out
    gemm_nt<<<dim3(LAT / 64, N_NODES / 64), 256>>>(p_h, lin_w, out + Z_OFF, N_NODES, LAT, HID_CH);

    k_zbias<<<(N_NODES * LAT + 255) / 256, 256>>>(out + Z_OFF, lin_b, bat);
    k_zg<<<(N_GRAPHS * LAT + 255) / 256, 256>>>(out + ZG_OFF);
    k_gout<<<N_GRAPHS, IN_CH>>>(out + ZG_OFF, dec_w, dec_b);
    k_xhat<<<(N_NODES * (IN_CH / 4) + 255) / 256, 256>>>(out + XH_OFF, bat);

    // a_hat = sigmoid(z z^T)
    k_ahat<<<dim3(N_NODES / 128, N_NODES / 128), 256>>>(out + Z_OFF, out + AH_OFF);
}

// round 4
// speedup vs baseline: 1.3306x; 1.3306x over previous
#include <cuda_runtime.h>
#include <cuda_bf16.h>
#include <cstdint>

#define N_NODES 16384
#define N_EDGES 262144
#define N_GRAPHS 16
#define IN_CH 128
#define HID_CH 256
#define LAT 64
#define MAXDEG 96

// d_out offsets (floats): z_node, z_graph, x_hat, a_hat
#define Z_OFF   0
#define ZG_OFF  (N_NODES*LAT)                    // 1048576
#define XH_OFF  (ZG_OFF + N_GRAPHS*LAT)          // 1049600
#define AH_OFF  (XH_OFF + N_NODES*IN_CH)         // 3146752

// ---------------- device scratch (no allocation allowed) ----------------
__device__ float g_h[N_NODES*HID_CH];     // 16 MB: h = x@gcn_w^T
__device__ float g_h2[N_NODES*HID_CH];    // 16 MB: relu(aggregated)
__device__ int   g_cnt_i[N_NODES];        // in-degree (excl. self loop)
__device__ int   g_cur[N_NODES];          // fill cursor
__device__ int   g_csr[N_NODES*MAXDEG];   // padded CSR: source node ids per target
__device__ float g_dinv[N_NODES];
__device__ float g_zgsum[N_GRAPHS*LAT];
__device__ float g_cnt[N_GRAPHS];
__device__ float g_gout[N_GRAPHS*IN_CH];

// ---------------- small helpers ----------------
__device__ __forceinline__ unsigned cvt_tf32(float x) {
    unsigned u;
    asm("cvt.rna.tf32.f32 %0, %1;" : "=r"(u) : "f"(x));
    return u;
}

__device__ __forceinline__ float sigf(float x) {
    float t;
    asm("tanh.approx.f32 %0, %1;" : "=f"(t) : "f"(x * 0.5f));
    return fmaf(0.5f, t, 0.5f);
}

__device__ __forceinline__ void mma_tf32(float* c, const unsigned* a, const unsigned* b) {
    asm volatile(
        "mma.sync.aligned.m16n8k8.row.col.f32.tf32.tf32.f32 "
        "{%0,%1,%2,%3},{%4,%5,%6,%7},{%8,%9},{%0,%1,%2,%3};\n"
        : "+f"(c[0]), "+f"(c[1]), "+f"(c[2]), "+f"(c[3])
        : "r"(a[0]), "r"(a[1]), "r"(a[2]), "r"(a[3]), "r"(b[0]), "r"(b[1]));
}

// ---------------- stage kernels ----------------
__global__ void k_zero() {
    int i = blockIdx.x * blockDim.x + threadIdx.x;
    if (i < N_NODES) { g_cnt_i[i] = 0; g_cur[i] = 0; }
    if (i < N_GRAPHS * LAT) g_zgsum[i] = 0.0f;
    if (i < N_GRAPHS) g_cnt[i] = 0.0f;
}

__global__ void k_cnt(const int* __restrict__ ei) {
    int e = blockIdx.x * blockDim.x + threadIdx.x;
    if (e < N_EDGES) atomicAdd(&g_cnt_i[ei[N_EDGES + e]], 1);
}

__global__ void k_count(const int* __restrict__ batch) {
    int i = blockIdx.x * blockDim.x + threadIdx.x;
    if (i < N_NODES) atomicAdd(&g_cnt[batch[i]], 1.0f);
}

__global__ void k_dinv() {
    int i = blockIdx.x * blockDim.x + threadIdx.x;
    if (i < N_NODES) g_dinv[i] = rsqrtf((float)(g_cnt_i[i] + 1));
}

__global__ void k_fill(const int* __restrict__ ei) {
    int e = blockIdx.x * blockDim.x + threadIdx.x;
    if (e < N_EDGES) {
        int row = ei[e];
        int col = ei[N_EDGES + e];
        int pos = atomicAdd(&g_cur[col], 1);
        g_csr[col * MAXDEG + pos] = row;
    }
}

// C[m][n] = sum_k A[m][k] * B[n][k]; A: MxK row-major, B: NxK row-major.
// Tile 64x64, 256 threads, 4x4 per thread, K chunked by 16.
__global__ __launch_bounds__(256) void gemm_nt(
    const float* __restrict__ A, const float* __restrict__ B,
    float* __restrict__ C, int M, int Nc, int K)
{
    __shared__ float As[16][68];
    __shared__ float Bs[16][68];
    int tid = threadIdx.x;
    int tx = tid & 15, ty = tid >> 4;
    int m0 = blockIdx.y * 64, n0 = blockIdx.x * 64;
    int lrow = tid >> 2, lq = (tid & 3) * 4;

    float acc[4][4];
#pragma unroll
    for (int i = 0; i < 4; i++)
#pragma unroll
        for (int j = 0; j < 4; j++) acc[i][j] = 0.0f;

    for (int k0 = 0; k0 < K; k0 += 16) {
        float4 va = *(const float4*)&A[(size_t)(m0 + lrow) * K + k0 + lq];
        float4 vb = *(const float4*)&B[(size_t)(n0 + lrow) * K + k0 + lq];
        __syncthreads();
        As[lq + 0][lrow] = va.x; As[lq + 1][lrow] = va.y;
        As[lq + 2][lrow] = va.z; As[lq + 3][lrow] = va.w;
        Bs[lq + 0][lrow] = vb.x; Bs[lq + 1][lrow] = vb.y;
        Bs[lq + 2][lrow] = vb.z; Bs[lq + 3][lrow] = vb.w;
        __syncthreads();
#pragma unroll
        for (int k = 0; k < 16; k++) {
            float4 a = *(float4*)&As[k][ty * 4];
            float4 b = *(float4*)&Bs[k][tx * 4];
            float av[4] = {a.x, a.y, a.z, a.w};
            float bv[4] = {b.x, b.y, b.z, b.w};
#pragma unroll
            for (int i = 0; i < 4; i++)
#pragma unroll
                for (int j = 0; j < 4; j++) acc[i][j] = fmaf(av[i], bv[j], acc[i][j]);
        }
    }
#pragma unroll
    for (int i = 0; i < 4; i++) {
        float4 v = make_float4(acc[i][0], acc[i][1], acc[i][2], acc[i][3]);
        *(float4*)&C[(size_t)(m0 + ty * 4 + i) * Nc + n0 + tx * 4] = v;
    }
}

// Fused gather + self-loop + bias + relu. One block (256 thr) per target node.
__global__ __launch_bounds__(256) void k_gather(const float* __restrict__ gcn_b) {
    int n = blockIdx.x;
    int c = threadIdx.x;
    int dg = g_cnt_i[n];
    float di = g_dinv[n];
    float acc = di * di * g_h[(size_t)n * HID_CH + c];   // self loop (norm = dinv^2)
    const int* lst = &g_csr[n * MAXDEG];
    int src = (dg > 0) ? lst[0] : 0;
    for (int e = 0; e < dg; e++) {
        int nsrc = (e + 1 < dg) ? lst[e + 1] : 0;
        float w = di * g_dinv[src];
        acc = fmaf(w, g_h[(size_t)src * HID_CH + c], acc);
        src = nsrc;
    }
    acc += gcn_b[c];
    g_h2[(size_t)n * HID_CH + c] = fmaxf(acc, 0.0f);
}

// add lin_b to z (in d_out), accumulate graph sums
__global__ void k_zbias(float* __restrict__ z, const float* __restrict__ lin_b,
                        const int* __restrict__ batch) {
    int i = blockIdx.x * blockDim.x + threadIdx.x;
    if (i < N_NODES * LAT) {
        int n = i / LAT, c = i % LAT;
        float v = z[i] + lin_b[c];
        z[i] = v;
        atomicAdd(&g_zgsum[batch[n] * LAT + c], v);
    }
}

__global__ void k_zg(float* __restrict__ zg_out) {
    int i = blockIdx.x * blockDim.x + threadIdx.x;
    if (i < N_GRAPHS * LAT) {
        int g = i / LAT;
        zg_out[i] = g_zgsum[i] / fmaxf(g_cnt[g], 1.0f);
    }
}

// g_out[g][c] = zg[g] . dec_w[c] + dec_b[c]
__global__ void k_gout(const float* __restrict__ zg, const float* __restrict__ dec_w,
                       const float* __restrict__ dec_b) {
    int g = blockIdx.x, c = threadIdx.x;
    float s = dec_b[c];
#pragma unroll 8
    for (int k = 0; k < LAT; k++) s = fmaf(zg[g * LAT + k], dec_w[c * LAT + k], s);
    g_gout[g * IN_CH + c] = s;
}

__global__ void k_xhat(float* __restrict__ xh, const int* __restrict__ batch) {
    int t = blockIdx.x * blockDim.x + threadIdx.x;   // N_NODES * 32 threads
    if (t < N_NODES * (IN_CH / 4)) {
        int n = t / (IN_CH / 4), q = t % (IN_CH / 4);
        int b = batch[n];
        float4 v = *(const float4*)&g_gout[b * IN_CH + q * 4];
        *(float4*)&xh[(size_t)n * IN_CH + q * 4] = v;
    }
}

// a_hat = sigmoid(Z @ Z^T), symmetric: compute upper-triangular 128x128 tiles only,
// store off-diagonal tiles twice (direct + transposed via smem staging).
// 8 warps (2x4), warp tile 64x32, K=64 in 2 halves of 32.
#define NT_TILES (N_NODES / 128)                 // 128
#define N_PAIRS  (NT_TILES * (NT_TILES + 1) / 2) // 8256
__global__ __launch_bounds__(256) void k_ahat(const float* __restrict__ z,
                                              float* __restrict__ out) {
    __shared__ union {
        struct { unsigned Zi[128][36]; unsigned Zj[128][36]; } ld;  // 36 KB
        float tr[64][132];                                          // 33 KB
    } sm;
    int tid = threadIdx.x;
    int warp = tid >> 5, lane = tid & 31;
    int wm = warp >> 2, wn = warp & 3;
    int r = lane >> 2, t4 = lane & 3;

    // decode upper-tri pair (bi <= bj) from linear block id
    int L = blockIdx.x;
    int bj = (int)((sqrtf(8.0f * (float)L + 1.0f) - 1.0f) * 0.5f);
    while ((bj + 1) * (bj + 2) / 2 <= L) bj++;
    while (bj * (bj + 1) / 2 > L) bj--;
    int bi = L - bj * (bj + 1) / 2;
    int mb = bi << 7, nb = bj << 7;

    float acc[4][4][4];
#pragma unroll
    for (int mt = 0; mt < 4; mt++)
#pragma unroll
        for (int nt = 0; nt < 4; nt++)
#pragma unroll
            for (int q = 0; q < 4; q++) acc[mt][nt][q] = 0.0f;

#pragma unroll
    for (int kh = 0; kh < 2; kh++) {
        __syncthreads();
#pragma unroll
        for (int f = 0; f < 4; f++) {
            int id = f * 256 + tid;          // 0..1023
            int row = id >> 3, q = id & 7;   // 8 float4 per row
            float4 vi = *(const float4*)&z[(size_t)(mb + row) * LAT + kh * 32 + q * 4];
            float4 vj = *(const float4*)&z[(size_t)(nb + row) * LAT + kh * 32 + q * 4];
            uint4 ui = make_uint4(cvt_tf32(vi.x), cvt_tf32(vi.y), cvt_tf32(vi.z), cvt_tf32(vi.w));
            uint4 uj = make_uint4(cvt_tf32(vj.x), cvt_tf32(vj.y), cvt_tf32(vj.z), cvt_tf32(vj.w));
            *(uint4*)&sm.ld.Zi[row][q * 4] = ui;
            *(uint4*)&sm.ld.Zj[row][q * 4] = uj;
        }
        __syncthreads();

#pragma unroll
        for (int k8 = 0; k8 < 4; k8++) {
            int kc = k8 * 8;
            unsigned a[4][4], b[4][2];
#pragma unroll
            for (int mt = 0; mt < 4; mt++) {
                int rb = wm * 64 + mt * 16;
                a[mt][0] = sm.ld.Zi[rb + r][kc + t4];
                a[mt][1] = sm.ld.Zi[rb + r + 8][kc + t4];
                a[mt][2] = sm.ld.Zi[rb + r][kc + t4 + 4];
                a[mt][3] = sm.ld.Zi[rb + r + 8][kc + t4 + 4];
            }
#pragma unroll
            for (int nt = 0; nt < 4; nt++) {
                int cb = wn * 32 + nt * 8;
                b[nt][0] = sm.ld.Zj[cb + r][kc + t4];
                b[nt][1] = sm.ld.Zj[cb + r][kc + t4 + 4];
            }
#pragma unroll
            for (int mt = 0; mt < 4; mt++)
#pragma unroll
                for (int nt = 0; nt < 4; nt++)
                    mma_tf32(acc[mt][nt], a[mt], b[nt]);
        }
    }

    // sigmoid in place
#pragma unroll
    for (int mt = 0; mt < 4; mt++)
#pragma unroll
        for (int nt = 0; nt < 4; nt++)
#pragma unroll
            for (int q = 0; q < 4; q++) acc[mt][nt][q] = sigf(acc[mt][nt][q]);

    // direct store of tile (mb, nb)
#pragma unroll
    for (int mt = 0; mt < 4; mt++) {
#pragma unroll
        for (int nt = 0; nt < 4; nt++) {
            int gm = mb + wm * 64 + mt * 16 + r;
            int gn = nb + wn * 32 + nt * 8 + t4 * 2;
            *(float2*)&out[(size_t)gm * N_NODES + gn] =
                make_float2(acc[mt][nt][0], acc[mt][nt][1]);
            *(float2*)&out[((size_t)gm + 8) * N_NODES + gn] =
                make_float2(acc[mt][nt][2], acc[mt][nt][3]);
        }
    }

    if (bi == bj) return;   // diagonal tile: symmetric, done

    // mirror store of tile (nb, mb): transpose via smem in 2 chunks of 64 cols
#pragma unroll
    for (int p = 0; p < 2; p++) {
        __syncthreads();
        if ((wn >> 1) == p) {
            int cbase = wn * 32 - p * 64;   // 0 or 32 within chunk
#pragma unroll
            for (int mt = 0; mt < 4; mt++) {
#pragma unroll
                for (int nt = 0; nt < 4; nt++) {
                    int cc = cbase + nt * 8 + t4 * 2;
                    int rm0 = wm * 64 + mt * 16 + r;
                    sm.tr[cc + 0][rm0]     = acc[mt][nt][0];
                    sm.tr[cc + 1][rm0]     = acc[mt][nt][1];
                    sm.tr[cc + 0][rm0 + 8] = acc[mt][nt][2];
                    sm.tr[cc + 1][rm0 + 8] = acc[mt][nt][3];
                }
            }
        }
        __syncthreads();
        // coalesced store: 64 rows x 128 cols of the transposed chunk
        int cc = tid >> 2;
#pragma unroll
        for (int j = 0; j < 8; j++) {
            int col = (tid & 3) * 4 + j * 16;
            float4 v = *(float4*)&sm.tr[cc][col];
            *(float4*)&out[(size_t)(nb + p * 64 + cc) * N_NODES + mb + col] = v;
        }
    }
}

// ---------------- launcher ----------------
extern "C" void kernel_launch(void* const* d_in, const int* in_sizes, int n_in,
                              void* d_out_v, int out_size) {
    (void)in_sizes; (void)n_in; (void)out_size;
    const float* x        = (const float*)d_in[0];
    const int* ei         = (const int*)d_in[1];
    const int* bat        = (const int*)d_in[2];
    const float* gcn_w    = (const float*)d_in[3];
    const float* gcn_b    = (const float*)d_in[4];
    const float* lin_w    = (const float*)d_in[5];
    const float* lin_b    = (const float*)d_in[6];
    const float* dec_w    = (const float*)d_in[7];
    const float* dec_b    = (const float*)d_in[8];
    float* out = (float*)d_out_v;

    float *p_h, *p_h2;
    cudaGetSymbolAddress((void**)&p_h, g_h);
    cudaGetSymbolAddress((void**)&p_h2, g_h2);

    k_zero<<<(N_NODES + 255) / 256, 256>>>();
    k_cnt<<<(N_EDGES + 255) / 256, 256>>>(ei);
    k_count<<<(N_NODES + 255) / 256, 256>>>(bat);
    k_dinv<<<(N_NODES + 255) / 256, 256>>>();
    k_fill<<<(N_EDGES + 255) / 256, 256>>>(ei);

    // h = x @ gcn_w^T  [16384,256]
    gemm_nt<<<dim3(HID_CH / 64, N_NODES / 64), 256>>>(x, gcn_w, p_h, N_NODES, HID_CH, IN_CH);

    // fused aggregate + self loop + bias + relu
    k_gather<<<N_NODES, 256>>>(gcn_b);

    // z = h2 @ lin_w^T  [16384,64] -> d_out
    gemm_nt<<<dim3(LAT / 64, N_NODES / 64), 256>>>(p_h2, lin_w, out + Z_OFF, N_NODES, LAT, HID_CH);

    k_zbias<<<(N_NODES * LAT + 255) / 256, 256>>>(out + Z_OFF, lin_b, bat);
    k_zg<<<(N_GRAPHS * LAT + 255) / 256, 256>>>(out + ZG_OFF);
    k_gout<<<N_GRAPHS, IN_CH>>>(out + ZG_OFF, dec_w, dec_b);
    k_xhat<<<(N_NODES * (IN_CH / 4) + 255) / 256, 256>>>(out + XH_OFF, bat);

    // a_hat = sigmoid(z z^T), symmetric upper-tri tiles
    k_ahat<<<N_PAIRS, 256>>>(out + Z_OFF, out + AH_OFF);
}

// round 5
// speedup vs baseline: 1.5612x; 1.1733x over previous
#include <cuda_runtime.h>
#include <cuda_bf16.h>
#include <cstdint>

#define N_NODES 16384
#define N_EDGES 262144
#define N_GRAPHS 16
#define IN_CH 128
#define HID_CH 256
#define LAT 64
#define MAXDEG 96

// d_out offsets (floats): z_node, z_graph, x_hat, a_hat
#define Z_OFF   0
#define ZG_OFF  (N_NODES*LAT)
#define XH_OFF  (ZG_OFF + N_GRAPHS*LAT)
#define AH_OFF  (XH_OFF + N_NODES*IN_CH)

// ---------------- device scratch ----------------
__device__ float g_aggx[N_NODES*IN_CH];    // 8 MB: Â @ x
__device__ float g_h2[N_NODES*HID_CH];     // 16 MB: relu((Âx) @ W^T + b)
__device__ int   g_cnt_i[N_NODES];         // in-degree (excl. self loop) == fill cursor
__device__ int   g_csr[N_NODES*MAXDEG];
__device__ float g_zgsum[N_GRAPHS*LAT];
__device__ float g_cnt[N_GRAPHS];
__device__ float g_gout[N_GRAPHS*IN_CH];

// ---------------- helpers ----------------
__device__ __forceinline__ unsigned cvt_tf32(float x) {
    unsigned u;
    asm("cvt.rna.tf32.f32 %0, %1;" : "=r"(u) : "f"(x));
    return u;
}
__device__ __forceinline__ float sigf(float x) {
    float t;
    asm("tanh.approx.f32 %0, %1;" : "=f"(t) : "f"(x * 0.5f));
    return fmaf(0.5f, t, 0.5f);
}
__device__ __forceinline__ void mma_tf32(float* c, const unsigned* a, const unsigned* b) {
    asm volatile(
        "mma.sync.aligned.m16n8k8.row.col.f32.tf32.tf32.f32 "
        "{%0,%1,%2,%3},{%4,%5,%6,%7},{%8,%9},{%0,%1,%2,%3};\n"
        : "+f"(c[0]), "+f"(c[1]), "+f"(c[2]), "+f"(c[3])
        : "r"(a[0]), "r"(a[1]), "r"(a[2]), "r"(a[3]), "r"(b[0]), "r"(b[1]));
}

// ---------------- prep ----------------
__global__ void k_zero() {
    int i = blockIdx.x * blockDim.x + threadIdx.x;
    if (i < N_NODES) g_cnt_i[i] = 0;
    if (i < N_GRAPHS * LAT) g_zgsum[i] = 0.0f;
    if (i < N_GRAPHS) g_cnt[i] = 0.0f;
}

// one pass: cursor == degree counter
__global__ void k_build(const int* __restrict__ ei) {
    int e = blockIdx.x * blockDim.x + threadIdx.x;
    if (e < N_EDGES) {
        int row = ei[e];
        int col = ei[N_EDGES + e];
        int pos = atomicAdd(&g_cnt_i[col], 1);
        if (pos < MAXDEG) g_csr[col * MAXDEG + pos] = row;
    }
}

// agg_x[n] = dinv_n^2 * x[n] + sum_e dinv_n*dinv_src * x[src]   (128 ch)
__global__ __launch_bounds__(128) void k_gatherx(const float* __restrict__ x) {
    __shared__ float w_s[MAXDEG];
    __shared__ int   s_s[MAXDEG];
    int n = blockIdx.x, c = threadIdx.x;
    int dg = min(g_cnt_i[n], MAXDEG);
    float di = rsqrtf((float)(dg + 1));
    const int* lst = &g_csr[n * MAXDEG];
    if (c < dg) {
        int src = lst[c];
        s_s[c] = src;
        w_s[c] = di * rsqrtf((float)(g_cnt_i[src] + 1));
    }
    __syncthreads();
    float acc = di * di * x[(size_t)n * IN_CH + c];
#pragma unroll 4
    for (int e = 0; e < dg; e++)
        acc = fmaf(w_s[e], x[(size_t)s_s[e] * IN_CH + c], acc);
    g_aggx[(size_t)n * IN_CH + c] = acc;
}

// ---------------- split-tf32 MMA GEMM ----------------
// C[m][n] = sum_k A[m][k]*B[n][k] (+bias[n], opt relu). fp32-accurate via hi/lo tf32.
// M-tile 128, N-tile NTILE (128 or 64). 8 warps 2x4. K chunk 16.
template<int NTILE, int KDIM, int MODE>   // MODE 0: bias+relu, 1: bias
__global__ __launch_bounds__(256) void gemm_mma(
    const float* __restrict__ A, const float* __restrict__ B,
    const float* __restrict__ bias, float* __restrict__ C, int ldc)
{
    constexpr int NT = NTILE / 32;        // n-frags per warp
    __shared__ unsigned Ahi[128][20], Alo[128][20];
    __shared__ unsigned Bhi[NTILE][20], Blo[NTILE][20];
    int tid = threadIdx.x;
    int warp = tid >> 5, lane = tid & 31;
    int wm = warp >> 2, wn = warp & 3;
    int r = lane >> 2, t4 = lane & 3;
    int m0 = blockIdx.y * 128, n0 = blockIdx.x * NTILE;

    float acc[4][NT][4];
#pragma unroll
    for (int mt = 0; mt < 4; mt++)
#pragma unroll
        for (int nt = 0; nt < NT; nt++)
#pragma unroll
            for (int q = 0; q < 4; q++) acc[mt][nt][q] = 0.0f;

    for (int kc = 0; kc < KDIM; kc += 16) {
        __syncthreads();
        {
            int row = tid >> 2, q = (tid & 3) * 4;
#pragma unroll
            for (int h = 0; h < 2; h++) {
                int rr = row + h * 64;
                float4 v = *(const float4*)&A[(size_t)(m0 + rr) * KDIM + kc + q];
                unsigned h0 = cvt_tf32(v.x), h1 = cvt_tf32(v.y),
                         h2 = cvt_tf32(v.z), h3 = cvt_tf32(v.w);
                Ahi[rr][q+0] = h0; Ahi[rr][q+1] = h1; Ahi[rr][q+2] = h2; Ahi[rr][q+3] = h3;
                Alo[rr][q+0] = cvt_tf32(v.x - __uint_as_float(h0));
                Alo[rr][q+1] = cvt_tf32(v.y - __uint_as_float(h1));
                Alo[rr][q+2] = cvt_tf32(v.z - __uint_as_float(h2));
                Alo[rr][q+3] = cvt_tf32(v.w - __uint_as_float(h3));
            }
            for (int i = tid; i < NTILE * 4; i += 256) {
                int rr = i >> 2, q = (i & 3) * 4;
                float4 v = *(const float4*)&B[(size_t)(n0 + rr) * KDIM + kc + q];
                unsigned h0 = cvt_tf32(v.x), h1 = cvt_tf32(v.y),
                         h2 = cvt_tf32(v.z), h3 = cvt_tf32(v.w);
                Bhi[rr][q+0] = h0; Bhi[rr][q+1] = h1; Bhi[rr][q+2] = h2; Bhi[rr][q+3] = h3;
                Blo[rr][q+0] = cvt_tf32(v.x - __uint_as_float(h0));
                Blo[rr][q+1] = cvt_tf32(v.y - __uint_as_float(h1));
                Blo[rr][q+2] = cvt_tf32(v.z - __uint_as_float(h2));
                Blo[rr][q+3] = cvt_tf32(v.w - __uint_as_float(h3));
            }
        }
        __syncthreads();
#pragma unroll
        for (int k8 = 0; k8 < 2; k8++) {
            int kk = k8 * 8;
            unsigned ah[4][4], al[4][4], bh[NT][2], bl[NT][2];
#pragma unroll
            for (int mt = 0; mt < 4; mt++) {
                int rb = wm * 64 + mt * 16;
                ah[mt][0] = Ahi[rb + r][kk + t4];     al[mt][0] = Alo[rb + r][kk + t4];
                ah[mt][1] = Ahi[rb + r + 8][kk + t4]; al[mt][1] = Alo[rb + r + 8][kk + t4];
                ah[mt][2] = Ahi[rb + r][kk + t4 + 4]; al[mt][2] = Alo[rb + r][kk + t4 + 4];
                ah[mt][3] = Ahi[rb + r + 8][kk + t4 + 4]; al[mt][3] = Alo[rb + r + 8][kk + t4 + 4];
            }
#pragma unroll
            for (int nt = 0; nt < NT; nt++) {
                int cb = wn * (NT * 8) + nt * 8;
                bh[nt][0] = Bhi[cb + r][kk + t4];     bl[nt][0] = Blo[cb + r][kk + t4];
                bh[nt][1] = Bhi[cb + r][kk + t4 + 4]; bl[nt][1] = Blo[cb + r][kk + t4 + 4];
            }
#pragma unroll
            for (int mt = 0; mt < 4; mt++)
#pragma unroll
                for (int nt = 0; nt < NT; nt++) {
                    mma_tf32(acc[mt][nt], ah[mt], bh[nt]);
                    mma_tf32(acc[mt][nt], ah[mt], bl[nt]);
                    mma_tf32(acc[mt][nt], al[mt], bh[nt]);
                }
        }
    }

#pragma unroll
    for (int mt = 0; mt < 4; mt++) {
#pragma unroll
        for (int nt = 0; nt < NT; nt++) {
            int gm = m0 + wm * 64 + mt * 16 + r;
            int gn = n0 + wn * (NT * 8) + nt * 8 + t4 * 2;
            float b0 = bias[gn], b1 = bias[gn + 1];
            float v0 = acc[mt][nt][0] + b0, v1 = acc[mt][nt][1] + b1;
            float v2 = acc[mt][nt][2] + b0, v3 = acc[mt][nt][3] + b1;
            if (MODE == 0) {
                v0 = fmaxf(v0, 0.f); v1 = fmaxf(v1, 0.f);
                v2 = fmaxf(v2, 0.f); v3 = fmaxf(v3, 0.f);
            }
            *(float2*)&C[(size_t)gm * ldc + gn] = make_float2(v0, v1);
            *(float2*)&C[((size_t)gm + 8) * ldc + gn] = make_float2(v2, v3);
        }
    }
}

// ---------------- pooled path ----------------
// run-length reduction over sorted batch: 128 nodes/block, 64 threads (c = tid)
__global__ __launch_bounds__(64) void k_zred(const float* __restrict__ z,
                                             const int* __restrict__ batch) {
    int c = threadIdx.x;
    int n0 = blockIdx.x * 128;
    int gp = batch[n0];
    float acc = 0.f, cnt = 0.f;
    for (int r = 0; r < 128; r++) {
        int n = n0 + r;
        int g = batch[n];
        float v = z[(size_t)n * LAT + c];
        if (g != gp) {
            atomicAdd(&g_zgsum[gp * LAT + c], acc);
            if (c == 0) atomicAdd(&g_cnt[gp], cnt);
            acc = 0.f; cnt = 0.f; gp = g;
        }
        acc += v; cnt += 1.f;
    }
    atomicAdd(&g_zgsum[gp * LAT + c], acc);
    if (c == 0) atomicAdd(&g_cnt[gp], cnt);
}

__global__ __launch_bounds__(128) void k_zg_gout(float* __restrict__ zg_out,
                                                 const float* __restrict__ dec_w,
                                                 const float* __restrict__ dec_b) {
    __shared__ float zg_s[LAT];
    int g = blockIdx.x, t = threadIdx.x;
    if (t < LAT) {
        float v = g_zgsum[g * LAT + t] / fmaxf(g_cnt[g], 1.0f);
        zg_s[t] = v;
        zg_out[g * LAT + t] = v;
    }
    __syncthreads();
    float s = dec_b[t];
#pragma unroll 8
    for (int k = 0; k < LAT; k++) s = fmaf(zg_s[k], dec_w[t * LAT + k], s);
    g_gout[g * IN_CH + t] = s;
}

__global__ void k_xhat(float* __restrict__ xh, const int* __restrict__ batch) {
    int t = blockIdx.x * blockDim.x + threadIdx.x;
    if (t < N_NODES * (IN_CH / 4)) {
        int n = t / (IN_CH / 4), q = t % (IN_CH / 4);
        int b = batch[n];
        float4 v = *(const float4*)&g_gout[b * IN_CH + q * 4];
        *(float4*)&xh[(size_t)n * IN_CH + q * 4] = v;
    }
}

// ---------------- a_hat = sigmoid(Z Z^T), symmetric upper-tri ----------------
#define NT_TILES (N_NODES / 128)
#define N_PAIRS  (NT_TILES * (NT_TILES + 1) / 2)
__global__ __launch_bounds__(256) void k_ahat(const float* __restrict__ z,
                                              float* __restrict__ out) {
    __shared__ union {
        struct { unsigned Zi[128][36]; unsigned Zj[128][36]; } ld;
        float tr[64][132];
    } sm;
    int tid = threadIdx.x;
    int warp = tid >> 5, lane = tid & 31;
    int wm = warp >> 2, wn = warp & 3;
    int r = lane >> 2, t4 = lane & 3;

    int L = blockIdx.x;
    int bj = (int)((sqrtf(8.0f * (float)L + 1.0f) - 1.0f) * 0.5f);
    while ((bj + 1) * (bj + 2) / 2 <= L) bj++;
    while (bj * (bj + 1) / 2 > L) bj--;
    int bi = L - bj * (bj + 1) / 2;
    int mb = bi << 7, nb = bj << 7;

    float acc[4][4][4];
#pragma unroll
    for (int mt = 0; mt < 4; mt++)
#pragma unroll
        for (int nt = 0; nt < 4; nt++)
#pragma unroll
            for (int q = 0; q < 4; q++) acc[mt][nt][q] = 0.0f;

#pragma unroll
    for (int kh = 0; kh < 2; kh++) {
        __syncthreads();
#pragma unroll
        for (int f = 0; f < 4; f++) {
            int id = f * 256 + tid;
            int row = id >> 3, q = id & 7;
            float4 vi = *(const float4*)&z[(size_t)(mb + row) * LAT + kh * 32 + q * 4];
            float4 vj = *(const float4*)&z[(size_t)(nb + row) * LAT + kh * 32 + q * 4];
            uint4 ui = make_uint4(cvt_tf32(vi.x), cvt_tf32(vi.y), cvt_tf32(vi.z), cvt_tf32(vi.w));
            uint4 uj = make_uint4(cvt_tf32(vj.x), cvt_tf32(vj.y), cvt_tf32(vj.z), cvt_tf32(vj.w));
            *(uint4*)&sm.ld.Zi[row][q * 4] = ui;
            *(uint4*)&sm.ld.Zj[row][q * 4] = uj;
        }
        __syncthreads();

#pragma unroll
        for (int k8 = 0; k8 < 4; k8++) {
            int kc = k8 * 8;
            unsigned a[4][4], b[4][2];
#pragma unroll
            for (int mt = 0; mt < 4; mt++) {
                int rb = wm * 64 + mt * 16;
                a[mt][0] = sm.ld.Zi[rb + r][kc + t4];
                a[mt][1] = sm.ld.Zi[rb + r + 8][kc + t4];
                a[mt][2] = sm.ld.Zi[rb + r][kc + t4 + 4];
                a[mt][3] = sm.ld.Zi[rb + r + 8][kc + t4 + 4];
            }
#pragma unroll
            for (int nt = 0; nt < 4; nt++) {
                int cb = wn * 32 + nt * 8;
                b[nt][0] = sm.ld.Zj[cb + r][kc + t4];
                b[nt][1] = sm.ld.Zj[cb + r][kc + t4 + 4];
            }
#pragma unroll
            for (int mt = 0; mt < 4; mt++)
#pragma unroll
                for (int nt = 0; nt < 4; nt++)
                    mma_tf32(acc[mt][nt], a[mt], b[nt]);
        }
    }

#pragma unroll
    for (int mt = 0; mt < 4; mt++)
#pragma unroll
        for (int nt = 0; nt < 4; nt++)
#pragma unroll
            for (int q = 0; q < 4; q++) acc[mt][nt][q] = sigf(acc[mt][nt][q]);

#pragma unroll
    for (int mt = 0; mt < 4; mt++) {
#pragma unroll
        for (int nt = 0; nt < 4; nt++) {
            int gm = mb + wm * 64 + mt * 16 + r;
            int gn = nb + wn * 32 + nt * 8 + t4 * 2;
            __stcs((float2*)&out[(size_t)gm * N_NODES + gn],
                   make_float2(acc[mt][nt][0], acc[mt][nt][1]));
            __stcs((float2*)&out[((size_t)gm + 8) * N_NODES + gn],
                   make_float2(acc[mt][nt][2], acc[mt][nt][3]));
        }
    }

    if (bi == bj) return;

#pragma unroll
    for (int p = 0; p < 2; p++) {
        __syncthreads();
        if ((wn >> 1) == p) {
            int cbase = wn * 32 - p * 64;
#pragma unroll
            for (int mt = 0; mt < 4; mt++) {
#pragma unroll
                for (int nt = 0; nt < 4; nt++) {
                    int cc = cbase + nt * 8 + t4 * 2;
                    int rm0 = wm * 64 + mt * 16 + r;
                    sm.tr[cc + 0][rm0]     = acc[mt][nt][0];
                    sm.tr[cc + 1][rm0]     = acc[mt][nt][1];
                    sm.tr[cc + 0][rm0 + 8] = acc[mt][nt][2];
                    sm.tr[cc + 1][rm0 + 8] = acc[mt][nt][3];
                }
            }
        }
        __syncthreads();
        int cc = tid >> 2;
#pragma unroll
        for (int j = 0; j < 8; j++) {
            int col = (tid & 3) * 4 + j * 16;
            float4 v = *(float4*)&sm.tr[cc][col];
            __stcs((float4*)&out[(size_t)(nb + p * 64 + cc) * N_NODES + mb + col], v);
        }
    }
}

// ---------------- launcher ----------------
extern "C" void kernel_launch(void* const* d_in, const int* in_sizes, int n_in,
                              void* d_out_v, int out_size) {
    (void)in_sizes; (void)n_in; (void)out_size;
    const float* x     = (const float*)d_in[0];
    const int* ei      = (const int*)d_in[1];
    const int* bat     = (const int*)d_in[2];
    const float* gcn_w = (const float*)d_in[3];
    const float* gcn_b = (const float*)d_in[4];
    const float* lin_w = (const float*)d_in[5];
    const float* lin_b = (const float*)d_in[6];
    const float* dec_w = (const float*)d_in[7];
    const float* dec_b = (const float*)d_in[8];
    float* out = (float*)d_out_v;

    float *p_aggx, *p_h2;
    cudaGetSymbolAddress((void**)&p_aggx, g_aggx);
    cudaGetSymbolAddress((void**)&p_h2, g_h2);

    k_zero<<<(N_NODES + 255) / 256, 256>>>();                        // 0
    k_build<<<(N_EDGES + 255) / 256, 256>>>(ei);                     // 1
    k_gatherx<<<N_NODES, 128>>>(x);                                  // 2
    // h2 = relu(aggx @ gcn_w^T + b)
    gemm_mma<128, IN_CH, 0><<<dim3(HID_CH / 128, N_NODES / 128), 256>>>(
        p_aggx, gcn_w, gcn_b, p_h2, HID_CH);                         // 3 (profiled)
    // z = h2 @ lin_w^T + lin_b
    gemm_mma<64, HID_CH, 1><<<dim3(1, N_NODES / 128), 256>>>(
        p_h2, lin_w, lin_b, out + Z_OFF, LAT);                       // 4
    // a_hat (only needs z)
    k_ahat<<<N_PAIRS, 256>>>(out + Z_OFF, out + AH_OFF);             // 5
    // pooled path
    k_zred<<<N_NODES / 128, 64>>>(out + Z_OFF, bat);                 // 6
    k_zg_gout<<<N_GRAPHS, 128>>>(out + ZG_OFF, dec_w, dec_b);        // 7
    k_xhat<<<(N_NODES * (IN_CH / 4) + 255) / 256, 256>>>(out + XH_OFF, bat); // 8
}